// round 12
// baseline (speedup 1.0000x reference)
#include <cuda_runtime.h>
#include <stdint.h>

// Problem constants (B=1024 batch, V=2 vars, M=256 latent, C=256 categories)
#define B_SZ   1024
#define M_SZ   256
#define C_SZ   256
#define NPAIR  65536          // M*M (k,m) pairs
#define CTAS   1024
#define PAIRS_PER_CTA 64      // NPAIR / CTAS  (64 aligned pairs -> single k)
#define NITER  32             // 2 pairs per iteration
#define THREADS 256
#define NSTAGE 4
#define W1_OFF 16777216LL     // M*M*C = offset of W[1] in floats

// Scratch (static __device__ array: zero-initialized at load; no allocation).
// g_acc is indexed by ORIGINAL sample index b; k2 reads then re-zeroes it so
// every graph replay (and the first correctness call) sees zeros.
__device__ float g_acc[B_SZ];

__device__ __forceinline__ unsigned smem_u32(const void* p) {
    return (unsigned)__cvta_generic_to_shared(p);
}

// ---------------------------------------------------------------------------
// Kernel 1: main accumulation, with the x1-sort folded in per-CTA.
//   Each CTA owns 64 consecutive (k,m) pairs (one k) and ALL 1024 samples.
//
//   Per-CTA prologue: counting-sort the 1024 samples by x1 locally (packed
//   records b<<16 | x0<<8 | x1; smem histogram + warp scan + atomic scatter).
//   The scatter's tie order is nondeterministic, but accumulation is keyed by
//   the ORIGINAL b carried in the record, so per-CTA sort divergence only
//   permutes lanes among equal x1 keys -> identical math, identical targets.
//   Sorted order makes the row1 gather near-broadcast in the inner loop.
//   Sort scratch aliases the pipeline buffer (records are register-resident
//   before the first cp.async writes stage 0).
//
//   Main loop: two pairs per 4KB stage, 4-deep cp.async.cg pipeline, ONE
//   __syncthreads per iteration. w_sum[k] is CTA-constant -> epilogue.
// ---------------------------------------------------------------------------
__global__ void __launch_bounds__(THREADS, 8)
k1_main(const int* __restrict__ x,
        const float* __restrict__ W, const float* __restrict__ w_sum) {
    // stage layout: [0:256) row0 of pair 2i, [256:512) row0 of pair 2i+1,
    //               [512:768) row1 of pair 2i, [768:1024) row1 of pair 2i+1
    __shared__ float buf[NSTAGE][4 * C_SZ];

    const int t = threadIdx.x;          // 0..255
    const int lane = t & 31;

    // ---- local counting sort (scratch aliased into buf) ----
    int* s_sort = (int*)&buf[1][0];     // 1024 sorted packed records
    int* s_hist = (int*)&buf[2][0];     // 256
    int* s_off  = (int*)&buf[2][256];   // 256
    int* s_wsum = (int*)&buf[2][512];   // 8

    s_hist[t] = 0;
    __syncthreads();

    const int2* x2 = (const int2*)x;
    int packed[4];
#pragma unroll
    for (int j = 0; j < 4; j++) {
        int b = t + 256 * j;
        int2 v = x2[b];                 // v.x = x0, v.y = x1
        packed[j] = (b << 16) | (v.x << 8) | v.y;
        atomicAdd(&s_hist[v.y], 1);
    }
    __syncthreads();

    {   // exclusive scan of the 256-bin histogram (8 warps, shuffle scan)
        int h = s_hist[t], v = h;
#pragma unroll
        for (int d = 1; d < 32; d <<= 1) {
            int n = __shfl_up_sync(0xffffffffu, v, d);
            if (lane >= d) v += n;
        }
        if (lane == 31) s_wsum[t >> 5] = v;
        __syncthreads();
        if (t == 0) {
            int s = 0;
#pragma unroll
            for (int i = 0; i < 8; i++) { int tmp = s_wsum[i]; s_wsum[i] = s; s += tmp; }
        }
        __syncthreads();
        s_off[t] = (v - h) + s_wsum[t >> 5];
        __syncthreads();
    }

#pragma unroll
    for (int j = 0; j < 4; j++) {
        int pos = atomicAdd(&s_off[packed[j] & 255], 1);
        s_sort[pos] = packed[j];
    }
    __syncthreads();

    int ix0[4], ix1[4], ib[4];
#pragma unroll
    for (int j = 0; j < 4; j++) {
        int p = s_sort[t + 256 * j];
        ix1[j] = p & 255;
        ix0[j] = (p >> 8) & 255;
        ib[j]  = p >> 16;
    }
    __syncthreads();   // records in registers; buf is now free for the pipeline

    // ---- pipelined accumulation ----
    const int q0 = blockIdx.x * PAIRS_PER_CTA;
    const float wk = __ldg(w_sum + (q0 >> 8));              // k constant per CTA
    const float* base0 = W + (long long)q0 * C_SZ;          // W0 rows
    const float* base1 = W + W1_OFF + (long long)q0 * C_SZ; // W1 rows

    float acc[4] = {0.f, 0.f, 0.f, 0.f};

    // one 16B cp.async per thread per iteration `it` into stage `s`:
    // t<128 covers the 512-float W0 span of pairs (2it,2it+1), t>=128 the W1 span.
#define ISSUE(s, it)                                                          \
    do {                                                                      \
        const float* _src = (t < 128) ? (base0 + (it) * 512 + t * 4)          \
                                      : (base1 + (it) * 512 + (t - 128) * 4); \
        unsigned _dst = smem_u32(&buf[s][(t < 128) ? (t * 4)                  \
                                                   : (512 + (t - 128) * 4)]); \
        asm volatile("cp.async.cg.shared.global [%0], [%1], 16;\n"            \
                     :: "r"(_dst), "l"(_src));                                \
    } while (0)

#pragma unroll
    for (int s = 0; s < NSTAGE - 1; s++) {
        ISSUE(s, s);
        asm volatile("cp.async.commit_group;\n");
    }

    for (int i = 0; i < NITER; i++) {
        asm volatile("cp.async.wait_group %0;\n" :: "n"(NSTAGE - 2));
        __syncthreads();   // stage i&3 visible to all; stage (i-1)&3 consumed

        const int ip = i + NSTAGE - 1;
        if (ip < NITER) ISSUE(ip & (NSTAGE - 1), ip);
        asm volatile("cp.async.commit_group;\n");   // (possibly empty) keeps count

        const float* s0 = buf[i & (NSTAGE - 1)];
#pragma unroll
        for (int j = 0; j < 4; j++) {
            float a0 = s0[ix0[j]];          // pair A row0 (random x0)
            float b0 = s0[512 + ix1[j]];    // pair A row1 (sorted -> broadcast)
            float a1 = s0[256 + ix0[j]];    // pair B row0
            float b1 = s0[768 + ix1[j]];    // pair B row1
            acc[j] = fmaf(a0, b0, acc[j]);
            acc[j] = fmaf(a1, b1, acc[j]);
        }
    }
#undef ISSUE

#pragma unroll
    for (int j = 0; j < 4; j++)
        atomicAdd(&g_acc[ib[j]], acc[j] * wk);   // keyed by ORIGINAL b
}

// ---------------------------------------------------------------------------
// Kernel 2: out[b] = log(acc[b]) and re-zero for the next replay.
// ---------------------------------------------------------------------------
__global__ void k2_final(float* __restrict__ out) {
    int i = blockIdx.x * blockDim.x + threadIdx.x;
    if (i < B_SZ) {
        out[i] = logf(g_acc[i]);
        g_acc[i] = 0.0f;
    }
}

// ---------------------------------------------------------------------------
// Inputs (metadata order): d_in[0]=x int32 [1024,2], d_in[1]=W fp32 [2,256,256,256],
// d_in[2]=w_sum fp32 [256]. Output: fp32 [1024].
// ---------------------------------------------------------------------------
extern "C" void kernel_launch(void* const* d_in, const int* in_sizes, int n_in,
                              void* d_out, int out_size) {
    (void)in_sizes; (void)n_in; (void)out_size;
    const int*   x     = (const int*)d_in[0];
    const float* W     = (const float*)d_in[1];
    const float* w_sum = (const float*)d_in[2];
    float*       out   = (float*)d_out;

    k1_main<<<CTAS, THREADS>>>(x, W, w_sum);
    k2_final<<<4, 256>>>(out);
}

// round 13
// speedup vs baseline: 2.1889x; 2.1889x over previous
#include <cuda_runtime.h>
#include <stdint.h>

// Problem constants (B=1024 batch, V=2 vars, M=256 latent, C=256 categories)
#define B_SZ   1024
#define M_SZ   256
#define C_SZ   256
#define NPAIR  65536          // M*M (k,m) pairs
#define CTAS   1024           // <= 148 SMs * 8 CTAs resident -> whole grid co-resident
#define PAIRS_PER_CTA 64      // NPAIR / CTAS (64 aligned pairs -> single k)
#define NITER  32             // 2 pairs per iteration
#define THREADS 256
#define NSTAGE 4
#define W1_OFF 16777216LL     // M*M*C = offset of W[1] in floats

// Static scratch (zero-initialized at load; no allocation).
// The epilogue CTA restores g_acc/g_cnt/g_flag to zero each launch, so every
// graph replay (and the first correctness call) sees the initial state.
__device__ float        g_acc[B_SZ];   // partial sums, indexed in SORTED order
__device__ int          g_xs0[B_SZ];   // x0 of sorted sample i
__device__ int          g_xs1[B_SZ];   // x1 of sorted sample i (sort key)
__device__ int          g_bidx[B_SZ];  // original b of sorted sample i
__device__ volatile int g_flag;        // sort published
__device__ int          g_cnt;         // CTA completion counter

__device__ __forceinline__ unsigned smem_u32(const void* p) {
    return (unsigned)__cvta_generic_to_shared(p);
}

// ---------------------------------------------------------------------------
// Single fused kernel.
//   All CTAs:  issue 3-stage cp.async prologue FIRST (independent of sort).
//   CTA 0:     counting-sort the 1024 samples by x1 (proven R7/R11 code, in
//              dedicated 2KB smem, NOT aliased with the pipeline buffer),
//              publish via release-fence + flag.
//   Others:    thread 0 spins on the flag (all CTAs are co-resident, so CTA 0
//              always runs -> no deadlock), acquire-fence, load indices (__ldcg).
//   Mainloop:  IDENTICAL to the proven R11 k1 (no extra live registers):
//              2 pairs / 4KB stage, 4-deep cp.async.cg pipeline, one
//              __syncthreads per iteration, w_sum[k] hoisted to the epilogue.
//   Epilogue:  atomicAdd into g_acc (sorted-slot keyed); completion counter;
//              the last CTA computes out[g_bidx[i]] = log(g_acc[i]), re-zeros
//              g_acc, and resets counter+flag for the next replay.
// ---------------------------------------------------------------------------
__global__ void __launch_bounds__(THREADS, 8)
k_fused(const int* __restrict__ x, const float* __restrict__ W,
        const float* __restrict__ w_sum, float* __restrict__ out) {
    // stage layout: [0:256) row0 of pair 2i, [256:512) row0 of pair 2i+1,
    //               [512:768) row1 of pair 2i, [768:1024) row1 of pair 2i+1
    __shared__ float buf[NSTAGE][4 * C_SZ];
    __shared__ int   s_hist[256];     // sort scratch (separate from buf!)
    __shared__ int   s_off[256];
    __shared__ int   s_wsum[8];

    const int t    = threadIdx.x;     // 0..255
    const int lane = t & 31;
    const int q0   = blockIdx.x * PAIRS_PER_CTA;
    const float wk = __ldg(w_sum + (q0 >> 8));              // k constant per CTA
    const float* base0 = W + (long long)q0 * C_SZ;          // W0 rows
    const float* base1 = W + W1_OFF + (long long)q0 * C_SZ; // W1 rows

    // one 16B cp.async per thread per iteration `it` into stage `s`:
    // t<128 covers the 512-float W0 span of pairs (2it,2it+1), t>=128 the W1 span.
#define ISSUE(s, it)                                                          \
    do {                                                                      \
        const float* _src = (t < 128) ? (base0 + (it) * 512 + t * 4)          \
                                      : (base1 + (it) * 512 + (t - 128) * 4); \
        unsigned _dst = smem_u32(&buf[s][(t < 128) ? (t * 4)                  \
                                                   : (512 + (t - 128) * 4)]); \
        asm volatile("cp.async.cg.shared.global [%0], [%1], 16;\n"            \
                     :: "r"(_dst), "l"(_src));                                \
    } while (0)

    // ---- prologue FIRST: DRAM pipeline fills while the sort runs ----
#pragma unroll
    for (int s = 0; s < NSTAGE - 1; s++) {
        ISSUE(s, s);
        asm volatile("cp.async.commit_group;\n");
    }

    // ---- sort (CTA 0) / wait (others) ----
    if (blockIdx.x == 0) {
        s_hist[t] = 0;
        __syncthreads();
        int px0[4], px1[4];
        const int2* x2 = (const int2*)x;
#pragma unroll
        for (int j = 0; j < 4; j++) {
            int2 v = x2[t + 256 * j];
            px0[j] = v.x; px1[j] = v.y;
            atomicAdd(&s_hist[v.y], 1);
        }
        __syncthreads();
        {   // exclusive scan of the 256-bin histogram (8 warps, shuffle scan)
            int h = s_hist[t], v = h;
#pragma unroll
            for (int d = 1; d < 32; d <<= 1) {
                int n = __shfl_up_sync(0xffffffffu, v, d);
                if (lane >= d) v += n;
            }
            if (lane == 31) s_wsum[t >> 5] = v;
            __syncthreads();
            if (t == 0) {
                int s = 0;
#pragma unroll
                for (int i = 0; i < 8; i++) { int tmp = s_wsum[i]; s_wsum[i] = s; s += tmp; }
            }
            __syncthreads();
            s_off[t] = (v - h) + s_wsum[t >> 5];
            __syncthreads();
        }
#pragma unroll
        for (int j = 0; j < 4; j++) {
            int pos = atomicAdd(&s_off[px1[j]], 1);
            g_xs0[pos]  = px0[j];
            g_xs1[pos]  = px1[j];
            g_bidx[pos] = t + 256 * j;
        }
        __syncthreads();
        if (t == 0) {
            __threadfence();            // release: sorted data before flag
            g_flag = 1;
        }
        __syncthreads();
    } else {
        if (t == 0) {
            while (g_flag == 0) { }     // volatile poll; CTA 0 is co-resident
            __threadfence();            // acquire: flag before data reads
        }
        __syncthreads();
    }

    // ---- load this thread's sample indices (L2, bypass any stale L1) ----
    int ix0[4], ix1[4];
#pragma unroll
    for (int j = 0; j < 4; j++) {
        ix0[j] = __ldcg(&g_xs0[t + 256 * j]);
        ix1[j] = __ldcg(&g_xs1[t + 256 * j]);
    }
    float acc[4] = {0.f, 0.f, 0.f, 0.f};

    // ---- mainloop (identical to proven R11) ----
    for (int i = 0; i < NITER; i++) {
        asm volatile("cp.async.wait_group %0;\n" :: "n"(NSTAGE - 2));
        __syncthreads();   // stage i&3 visible to all; stage (i-1)&3 consumed

        const int ip = i + NSTAGE - 1;
        if (ip < NITER) ISSUE(ip & (NSTAGE - 1), ip);
        asm volatile("cp.async.commit_group;\n");   // (possibly empty) keeps count

        const float* s0 = buf[i & (NSTAGE - 1)];
#pragma unroll
        for (int j = 0; j < 4; j++) {
            float a0 = s0[ix0[j]];          // pair A row0 (random x0)
            float b0 = s0[512 + ix1[j]];    // pair A row1 (sorted -> broadcast)
            float a1 = s0[256 + ix0[j]];    // pair B row0
            float b1 = s0[768 + ix1[j]];    // pair B row1
            acc[j] = fmaf(a0, b0, acc[j]);
            acc[j] = fmaf(a1, b1, acc[j]);
        }
    }
#undef ISSUE

#pragma unroll
    for (int j = 0; j < 4; j++)
        atomicAdd(&g_acc[t + 256 * j], acc[j] * wk);

    // ---- completion counter; last CTA does the log epilogue + state reset ----
    __shared__ int s_last;
    __threadfence();                     // release: g_acc adds before counter
    if (t == 0) {
        int c = atomicAdd(&g_cnt, 1);
        s_last = (c == CTAS - 1);
    }
    __syncthreads();
    if (s_last) {
        __threadfence();                 // acquire: counter before g_acc reads
#pragma unroll
        for (int j = 0; j < 4; j++) {
            int i = t + 256 * j;
            out[g_bidx[i]] = logf(__ldcg(&g_acc[i]));
        }
        __syncthreads();
#pragma unroll
        for (int j = 0; j < 4; j++) g_acc[t + 256 * j] = 0.0f;
        __syncthreads();
        if (t == 0) {
            g_cnt = 0;
            __threadfence();
            g_flag = 0;                  // reset for next graph replay
        }
    }
}

// ---------------------------------------------------------------------------
// Inputs (metadata order): d_in[0]=x int32 [1024,2], d_in[1]=W fp32 [2,256,256,256],
// d_in[2]=w_sum fp32 [256]. Output: fp32 [1024].
// ---------------------------------------------------------------------------
extern "C" void kernel_launch(void* const* d_in, const int* in_sizes, int n_in,
                              void* d_out, int out_size) {
    (void)in_sizes; (void)n_in; (void)out_size;
    const int*   x     = (const int*)d_in[0];
    const float* W     = (const float*)d_in[1];
    const float* w_sum = (const float*)d_in[2];
    float*       out   = (float*)d_out;

    k_fused<<<CTAS, THREADS>>>(x, W, w_sum, out);
}

// round 14
// speedup vs baseline: 2.1946x; 1.0026x over previous
#include <cuda_runtime.h>
#include <stdint.h>

// Problem constants (B=1024 batch, V=2 vars, M=256 latent, C=256 categories)
#define B_SZ   1024
#define M_SZ   256
#define C_SZ   256
#define NPAIR  65536          // M*M (k,m) pairs
#define CTAS   1024           // <= 148 SMs * 8 CTAs resident -> whole grid co-resident
#define PAIRS_PER_CTA 64      // NPAIR / CTAS (64 aligned pairs -> single k)
#define NITER  32             // 2 pairs per iteration
#define THREADS 256
#define NSTAGE 4
#define W1_OFF 16777216LL     // M*M*C = offset of W[1] in floats

// Static scratch (zero-initialized at load; no allocation).
// The epilogue CTA restores g_acc/g_cnt/g_flag to zero each launch, so every
// graph replay (and the first correctness call) sees the initial state.
__device__ float        g_acc[B_SZ];   // partial sums, indexed in SORTED order
__device__ int          g_xs0[B_SZ];   // x0 of sorted sample i
__device__ int          g_xs1[B_SZ];   // x1 of sorted sample i (sort key)
__device__ int          g_bidx[B_SZ];  // original b of sorted sample i
__device__ volatile int g_flag;        // sort published
__device__ int          g_cnt;         // CTA completion counter

__device__ __forceinline__ unsigned smem_u32(const void* p) {
    return (unsigned)__cvta_generic_to_shared(p);
}

// ---------------------------------------------------------------------------
// Single fused kernel.
//   All CTAs:  issue 3-stage cp.async prologue FIRST (independent of sort).
//   CTA 0:     counting-sort the 1024 samples by x1 (proven R7/R11 code, in
//              dedicated 2KB smem, NOT aliased with the pipeline buffer),
//              publish via release-fence + flag.
//   Others:    thread 0 spins on the flag (all CTAs are co-resident, so CTA 0
//              always runs -> no deadlock), acquire-fence, load indices (__ldcg).
//   Mainloop:  IDENTICAL to the proven R11 k1 (no extra live registers):
//              2 pairs / 4KB stage, 4-deep cp.async.cg pipeline, one
//              __syncthreads per iteration, w_sum[k] hoisted to the epilogue.
//   Epilogue:  atomicAdd into g_acc (sorted-slot keyed); completion counter;
//              the last CTA computes out[g_bidx[i]] = log(g_acc[i]), re-zeros
//              g_acc, and resets counter+flag for the next replay.
// ---------------------------------------------------------------------------
__global__ void __launch_bounds__(THREADS, 8)
k_fused(const int* __restrict__ x, const float* __restrict__ W,
        const float* __restrict__ w_sum, float* __restrict__ out) {
    // stage layout: [0:256) row0 of pair 2i, [256:512) row0 of pair 2i+1,
    //               [512:768) row1 of pair 2i, [768:1024) row1 of pair 2i+1
    __shared__ float buf[NSTAGE][4 * C_SZ];
    __shared__ int   s_hist[256];     // sort scratch (separate from buf!)
    __shared__ int   s_off[256];
    __shared__ int   s_wsum[8];

    const int t    = threadIdx.x;     // 0..255
    const int lane = t & 31;
    const int q0   = blockIdx.x * PAIRS_PER_CTA;
    const float wk = __ldg(w_sum + (q0 >> 8));              // k constant per CTA
    const float* base0 = W + (long long)q0 * C_SZ;          // W0 rows
    const float* base1 = W + W1_OFF + (long long)q0 * C_SZ; // W1 rows

    // one 16B cp.async per thread per iteration `it` into stage `s`:
    // t<128 covers the 512-float W0 span of pairs (2it,2it+1), t>=128 the W1 span.
#define ISSUE(s, it)                                                          \
    do {                                                                      \
        const float* _src = (t < 128) ? (base0 + (it) * 512 + t * 4)          \
                                      : (base1 + (it) * 512 + (t - 128) * 4); \
        unsigned _dst = smem_u32(&buf[s][(t < 128) ? (t * 4)                  \
                                                   : (512 + (t - 128) * 4)]); \
        asm volatile("cp.async.cg.shared.global [%0], [%1], 16;\n"            \
                     :: "r"(_dst), "l"(_src));                                \
    } while (0)

    // ---- prologue FIRST: DRAM pipeline fills while the sort runs ----
#pragma unroll
    for (int s = 0; s < NSTAGE - 1; s++) {
        ISSUE(s, s);
        asm volatile("cp.async.commit_group;\n");
    }

    // ---- sort (CTA 0) / wait (others) ----
    if (blockIdx.x == 0) {
        s_hist[t] = 0;
        __syncthreads();
        int px0[4], px1[4];
        const int2* x2 = (const int2*)x;
#pragma unroll
        for (int j = 0; j < 4; j++) {
            int2 v = x2[t + 256 * j];
            px0[j] = v.x; px1[j] = v.y;
            atomicAdd(&s_hist[v.y], 1);
        }
        __syncthreads();
        {   // exclusive scan of the 256-bin histogram (8 warps, shuffle scan)
            int h = s_hist[t], v = h;
#pragma unroll
            for (int d = 1; d < 32; d <<= 1) {
                int n = __shfl_up_sync(0xffffffffu, v, d);
                if (lane >= d) v += n;
            }
            if (lane == 31) s_wsum[t >> 5] = v;
            __syncthreads();
            if (t == 0) {
                int s = 0;
#pragma unroll
                for (int i = 0; i < 8; i++) { int tmp = s_wsum[i]; s_wsum[i] = s; s += tmp; }
            }
            __syncthreads();
            s_off[t] = (v - h) + s_wsum[t >> 5];
            __syncthreads();
        }
#pragma unroll
        for (int j = 0; j < 4; j++) {
            int pos = atomicAdd(&s_off[px1[j]], 1);
            g_xs0[pos]  = px0[j];
            g_xs1[pos]  = px1[j];
            g_bidx[pos] = t + 256 * j;
        }
        __syncthreads();
        if (t == 0) {
            __threadfence();            // release: sorted data before flag
            g_flag = 1;
        }
        __syncthreads();
    } else {
        if (t == 0) {
            while (g_flag == 0) { }     // volatile poll; CTA 0 is co-resident
            __threadfence();            // acquire: flag before data reads
        }
        __syncthreads();
    }

    // ---- load this thread's sample indices (L2, bypass any stale L1) ----
    int ix0[4], ix1[4];
#pragma unroll
    for (int j = 0; j < 4; j++) {
        ix0[j] = __ldcg(&g_xs0[t + 256 * j]);
        ix1[j] = __ldcg(&g_xs1[t + 256 * j]);
    }
    float acc[4] = {0.f, 0.f, 0.f, 0.f};

    // ---- mainloop (identical to proven R11) ----
    for (int i = 0; i < NITER; i++) {
        asm volatile("cp.async.wait_group %0;\n" :: "n"(NSTAGE - 2));
        __syncthreads();   // stage i&3 visible to all; stage (i-1)&3 consumed

        const int ip = i + NSTAGE - 1;
        if (ip < NITER) ISSUE(ip & (NSTAGE - 1), ip);
        asm volatile("cp.async.commit_group;\n");   // (possibly empty) keeps count

        const float* s0 = buf[i & (NSTAGE - 1)];
#pragma unroll
        for (int j = 0; j < 4; j++) {
            float a0 = s0[ix0[j]];          // pair A row0 (random x0)
            float b0 = s0[512 + ix1[j]];    // pair A row1 (sorted -> broadcast)
            float a1 = s0[256 + ix0[j]];    // pair B row0
            float b1 = s0[768 + ix1[j]];    // pair B row1
            acc[j] = fmaf(a0, b0, acc[j]);
            acc[j] = fmaf(a1, b1, acc[j]);
        }
    }
#undef ISSUE

#pragma unroll
    for (int j = 0; j < 4; j++)
        atomicAdd(&g_acc[t + 256 * j], acc[j] * wk);

    // ---- completion counter; last CTA does the log epilogue + state reset ----
    __shared__ int s_last;
    __threadfence();                     // release: g_acc adds before counter
    if (t == 0) {
        int c = atomicAdd(&g_cnt, 1);
        s_last = (c == CTAS - 1);
    }
    __syncthreads();
    if (s_last) {
        __threadfence();                 // acquire: counter before g_acc reads
#pragma unroll
        for (int j = 0; j < 4; j++) {
            int i = t + 256 * j;
            out[g_bidx[i]] = logf(__ldcg(&g_acc[i]));
        }
        __syncthreads();
#pragma unroll
        for (int j = 0; j < 4; j++) g_acc[t + 256 * j] = 0.0f;
        __syncthreads();
        if (t == 0) {
            g_cnt = 0;
            __threadfence();
            g_flag = 0;                  // reset for next graph replay
        }
    }
}

// ---------------------------------------------------------------------------
// Inputs (metadata order): d_in[0]=x int32 [1024,2], d_in[1]=W fp32 [2,256,256,256],
// d_in[2]=w_sum fp32 [256]. Output: fp32 [1024].
// ---------------------------------------------------------------------------
extern "C" void kernel_launch(void* const* d_in, const int* in_sizes, int n_in,
                              void* d_out, int out_size) {
    (void)in_sizes; (void)n_in; (void)out_size;
    const int*   x     = (const int*)d_in[0];
    const float* W     = (const float*)d_in[1];
    const float* w_sum = (const float*)d_in[2];
    float*       out   = (float*)d_out;

    k_fused<<<CTAS, THREADS>>>(x, W, w_sum, out);
}